// round 1
// baseline (speedup 1.0000x reference)
#include <cuda_runtime.h>
#include <cstdint>
#include <cfloat>

// Problem constants
#define N_ROWS 32768      // 32 * 32 * 32  (b * h * w)
#define C_DIM  256
#define K_CODES 1024
#define TR 64             // rows per block tile
#define TK 64             // codes per chunk
#define LD 260            // padded smem row stride (floats): 4*LD mod 32 banks = 16 -> conflict-lite
#define N_CHUNKS (K_CODES / TK)

#define SMEM_MAIN   (3 * TR * LD * 4)      // z tile + 2 emb buffers = 199,680 B
#define SMEM_GATHER (128 * 257 * 4)        // 131,584 B

__device__ int   g_idx[N_ROWS];
__device__ float g_enorm[K_CODES];
__device__ float g_partial[256];

__device__ __forceinline__ void fma2(unsigned long long &d, unsigned long long a, unsigned long long b) {
    asm("fma.rn.f32x2 %0, %1, %2, %3;" : "=l"(d) : "l"(a), "l"(b), "l"(d));
}
__device__ __forceinline__ unsigned smem_u32(const void* p) {
    return (unsigned)__cvta_generic_to_shared(p);
}
__device__ __forceinline__ void cp16(unsigned dst, const void* src) {
    asm volatile("cp.async.cg.shared.global [%0], [%1], 16;" :: "r"(dst), "l"(src));
}

// ---------------------------------------------------------------------------
// Kernel 1: codebook squared norms
// ---------------------------------------------------------------------------
__global__ void k_enorm(const float* __restrict__ emb) {
    int code = blockIdx.x * 8 + (threadIdx.x >> 5);
    int lane = threadIdx.x & 31;
    const float4* p = (const float4*)(emb + code * C_DIM);
    float4 a = p[lane];
    float4 b = p[lane + 32];
    float s = a.x*a.x + a.y*a.y + a.z*a.z + a.w*a.w
            + b.x*b.x + b.y*b.y + b.z*b.z + b.w*b.w;
    #pragma unroll
    for (int m = 16; m; m >>= 1) s += __shfl_xor_sync(0xffffffffu, s, m);
    if (lane == 0) g_enorm[code] = s;
}

// ---------------------------------------------------------------------------
// Kernel 2: distance GEMM + argmin.
// Block = 64 rows x all 1024 codes (16 chunks of 64, double-buffered cp.async).
// Thread (tx=tid&15, ty=tid>>4) owns rows {ty+16i} x codes {tx+16j}, i,j in 0..3.
// K-dim vectorized in f32x2 pairs: acc holds (even-c sum, odd-c sum).
// ---------------------------------------------------------------------------
__global__ void __launch_bounds__(256, 1)
k_main(const float* __restrict__ z_e, const float* __restrict__ emb,
       float* __restrict__ out_idx_f)
{
    extern __shared__ float sm[];
    float* z_s  = sm;                   // TR x LD
    float* e_s0 = sm + TR * LD;         // TK x LD
    float* e_s1 = e_s0 + TK * LD;       // TK x LD

    const int tid = threadIdx.x;
    const int tx = tid & 15, ty = tid >> 4;
    const int r0  = blockIdx.x * TR;
    const int b   = r0 >> 10;
    const int hw0 = r0 & 1023;

    // prologue: async-load emb chunk 0
    {
        for (int i = tid; i < TK * 64; i += 256) {
            int code = i >> 6, c4 = (i & 63) << 2;
            cp16(smem_u32(e_s0 + code * LD + c4), emb + code * C_DIM + c4);
        }
        asm volatile("cp.async.commit_group;");
    }
    // z tile: transpose NCHW -> [row][c] in smem (coalesced global reads over hw)
    for (int i = tid; i < C_DIM * TR; i += 256) {
        int c = i >> 6, r = i & 63;
        z_s[r * LD + c] = z_e[(((size_t)(b * C_DIM + c)) << 10) + hw0 + r];
    }

    float best[4];
    int   bidx[4];
    #pragma unroll
    for (int i = 0; i < 4; i++) { best[i] = FLT_MAX; bidx[i] = 0x7fffffff; }

    for (int ch = 0; ch < N_CHUNKS; ch++) {
        asm volatile("cp.async.wait_group 0;");
        __syncthreads();
        const float* eb = (ch & 1) ? e_s1 : e_s0;
        if (ch + 1 < N_CHUNKS) {
            float* nb = (ch & 1) ? e_s0 : e_s1;
            const float* src = emb + (size_t)(ch + 1) * TK * C_DIM;
            for (int i = tid; i < TK * 64; i += 256) {
                int code = i >> 6, c4 = (i & 63) << 2;
                cp16(smem_u32(nb + code * LD + c4), src + code * C_DIM + c4);
            }
            asm volatile("cp.async.commit_group;");
        }

        unsigned long long acc[4][4];
        #pragma unroll
        for (int i = 0; i < 4; i++)
            #pragma unroll
            for (int j = 0; j < 4; j++) acc[i][j] = 0ull;

        const float* zr0 = z_s + ty * LD;
        const float* er0 = eb  + tx * LD;

        #pragma unroll 2
        for (int c = 0; c < C_DIM; c += 4) {
            ulonglong2 zv[4], ev[4];
            #pragma unroll
            for (int i = 0; i < 4; i++)
                zv[i] = *(const ulonglong2*)(zr0 + i * 16 * LD + c);
            #pragma unroll
            for (int j = 0; j < 4; j++)
                ev[j] = *(const ulonglong2*)(er0 + j * 16 * LD + c);
            #pragma unroll
            for (int i = 0; i < 4; i++)
                #pragma unroll
                for (int j = 0; j < 4; j++) {
                    fma2(acc[i][j], zv[i].x, ev[j].x);
                    fma2(acc[i][j], zv[i].y, ev[j].y);
                }
        }

        // epilogue: dist = ||e||^2 - 2 z.e  (||z||^2 is argmin-invariant)
        #pragma unroll
        for (int j = 0; j < 4; j++) {
            int k = ch * TK + tx + 16 * j;
            float en = g_enorm[k];
            #pragma unroll
            for (int i = 0; i < 4; i++) {
                float lo = __uint_as_float((unsigned)acc[i][j]);
                float hi = __uint_as_float((unsigned)(acc[i][j] >> 32));
                float d = en - 2.0f * (lo + hi);
                if (d < best[i] || (d == best[i] && k < bidx[i])) {
                    best[i] = d; bidx[i] = k;
                }
            }
        }
    }

    // reduce argmin across tx (lanes 0-15 and 16-31 are separate ty groups)
    #pragma unroll
    for (int i = 0; i < 4; i++) {
        float bv = best[i];
        int   bi = bidx[i];
        #pragma unroll
        for (int m = 1; m < 16; m <<= 1) {
            float ov = __shfl_xor_sync(0xffffffffu, bv, m);
            int   oi = __shfl_xor_sync(0xffffffffu, bi, m);
            if (ov < bv || (ov == bv && oi < bi)) { bv = ov; bi = oi; }
        }
        if (tx == 0) {
            int row = ty + 16 * i;
            g_idx[r0 + row]     = bi;
            out_idx_f[r0 + row] = (float)bi;
        }
    }
}

// ---------------------------------------------------------------------------
// Kernel 3: gather z_q = emb[idx], write res in NCHW, accumulate sq-diff.
// Block = 128 rows (one b, contiguous hw). emb rows staged via smem so both
// the gather read and the NCHW write are coalesced.
// ---------------------------------------------------------------------------
__global__ void __launch_bounds__(256)
k_gather(const float* __restrict__ z_e, const float* __restrict__ emb,
         float* __restrict__ res)
{
    extern __shared__ float esm[];      // 128 x 257
    __shared__ int   idx_sm[128];
    __shared__ float wsum[8];

    const int tid = threadIdx.x;
    const int r0  = blockIdx.x * 128;
    const int b   = r0 >> 10;
    const int hw0 = r0 & 1023;

    if (tid < 128) idx_sm[tid] = g_idx[r0 + tid];
    __syncthreads();

    // stage 128 codebook rows, fully coalesced (one emb row per 256-thread pass)
    for (int i = tid; i < 128 * 256; i += 256) {
        int r = i >> 8, c = i & 255;
        esm[r * 257 + c] = emb[idx_sm[r] * C_DIM + c];
    }
    __syncthreads();

    float acc = 0.0f;
    const int r     = tid & 127;
    const int chalf = tid >> 7;
    for (int cc = 0; cc < 256; cc += 2) {
        int c = cc + chalf;
        float v = esm[r * 257 + c];                      // bank conflict-free (pad 257)
        size_t gi = (((size_t)(b * C_DIM + c)) << 10) + hw0 + r;
        float zv = z_e[gi];
        res[gi] = v;                                     // coalesced 512B stores
        float df = v - zv;
        acc += df * df;
    }

    // deterministic block reduce
    #pragma unroll
    for (int m = 16; m; m >>= 1) acc += __shfl_xor_sync(0xffffffffu, acc, m);
    if ((tid & 31) == 0) wsum[tid >> 5] = acc;
    __syncthreads();
    if (tid == 0) {
        float s = 0.0f;
        #pragma unroll
        for (int w = 0; w < 8; w++) s += wsum[w];
        g_partial[blockIdx.x] = s;
    }
}

// ---------------------------------------------------------------------------
// Kernel 4: final loss = 1.25 * mean(sq-diff)   (deterministic tree reduce)
// ---------------------------------------------------------------------------
__global__ void k_loss(float* __restrict__ out_loss) {
    __shared__ float s[256];
    int tid = threadIdx.x;
    s[tid] = g_partial[tid];
    __syncthreads();
    for (int st = 128; st > 0; st >>= 1) {
        if (tid < st) s[tid] += s[tid + st];
        __syncthreads();
    }
    if (tid == 0) out_loss[0] = 1.25f * (s[0] / 8388608.0f);
}

// ---------------------------------------------------------------------------
extern "C" void kernel_launch(void* const* d_in, const int* in_sizes, int n_in,
                              void* d_out, int out_size)
{
    const float* z_e = (const float*)d_in[0];   // (32, 256, 32, 32) fp32
    const float* emb = (const float*)d_in[1];   // (1024, 256) fp32

    float* out  = (float*)d_out;
    float* res  = out;                           // 8,388,608 floats
    float* loss = out + 8388608;                 // 1 float
    float* idxf = out + 8388609;                 // 32,768 floats (indices)

    cudaFuncSetAttribute(k_main,   cudaFuncAttributeMaxDynamicSharedMemorySize, SMEM_MAIN);
    cudaFuncSetAttribute(k_gather, cudaFuncAttributeMaxDynamicSharedMemorySize, SMEM_GATHER);

    k_enorm <<<K_CODES / 8, 256>>>(emb);
    k_main  <<<N_ROWS / TR, 256, SMEM_MAIN>>>(z_e, emb, idxf);
    k_gather<<<N_ROWS / 128, 256, SMEM_GATHER>>>(z_e, emb, res);
    k_loss  <<<1, 256>>>(loss);
}

// round 2
// speedup vs baseline: 1.2243x; 1.2243x over previous
#include <cuda_runtime.h>
#include <cstdint>
#include <cfloat>

typedef unsigned long long ull;

#define N_ROWS 32768      // 32 * 32 * 32  (b * h * w)
#define C_DIM  256
#define K_CODES 1024

// k_main2 tiling
#define BR 128            // rows per block
#define BK 128            // codes per block
#define PC 64             // c-panel size
#define NPAN (C_DIM / PC) // 4
#define NCB (K_CODES / BK) // 8 code-blocks

#define ZPAN (PC * BR)                       // 8192 floats
#define SMEM_MAIN (4 * ZPAN * 4)             // z0,z1,e0,e1 = 131072 B
#define SMEM_GATHER (128 * 257 * 4)          // 131584 B

__device__ float g_embT2[C_DIM * K_CODES];   // (-2*emb)^T : [c][code]
__device__ float g_enorm[K_CODES];
__device__ int   g_idx[N_ROWS];
__device__ float g_pd[NCB * N_ROWS];         // partial best dist per code-block
__device__ int   g_pi[NCB * N_ROWS];         // partial best idx
__device__ float g_partial[256];

__device__ __forceinline__ void fma2(ull &d, ull a, ull b) {
    asm("fma.rn.f32x2 %0, %1, %2, %0;" : "+l"(d) : "l"(a), "l"(b));
}
__device__ __forceinline__ ull dup2(float x) {
    ull r; asm("mov.b64 %0, {%1, %1};" : "=l"(r) : "f"(x)); return r;
}
__device__ __forceinline__ unsigned smem_u32(const void* p) {
    return (unsigned)__cvta_generic_to_shared(p);
}
__device__ __forceinline__ void cp16(unsigned dst, const void* src) {
    asm volatile("cp.async.cg.shared.global [%0], [%1], 16;" :: "r"(dst), "l"(src));
}

// ---------------------------------------------------------------------------
// Kernel 1: codebook squared norms
// ---------------------------------------------------------------------------
__global__ void k_enorm(const float* __restrict__ emb) {
    int code = blockIdx.x * 8 + (threadIdx.x >> 5);
    int lane = threadIdx.x & 31;
    const float4* p = (const float4*)(emb + code * C_DIM);
    float4 a = p[lane];
    float4 b = p[lane + 32];
    float s = a.x*a.x + a.y*a.y + a.z*a.z + a.w*a.w
            + b.x*b.x + b.y*b.y + b.z*b.z + b.w*b.w;
    #pragma unroll
    for (int m = 16; m; m >>= 1) s += __shfl_xor_sync(0xffffffffu, s, m);
    if (lane == 0) g_enorm[code] = s;
}

// ---------------------------------------------------------------------------
// Kernel 2: transpose + scale: g_embT2[c][k] = -2 * emb[k][c]
// ---------------------------------------------------------------------------
__global__ void k_transpose(const float* __restrict__ emb) {
    __shared__ float t[32 * 260];
    int tid = threadIdx.x;
    int cb = blockIdx.x;                 // 32 codes per block
    for (int i = tid; i < 32 * 256; i += 256) {
        int code = i >> 8, c = i & 255;  // c fastest -> coalesced reads
        t[code * 260 + c] = emb[(cb * 32 + code) * C_DIM + c];
    }
    __syncthreads();
    for (int i = tid; i < 32 * 256; i += 256) {
        int c = i >> 5, code = i & 31;   // code fastest -> 128B store txns
        g_embT2[c * K_CODES + cb * 32 + code] = -2.0f * t[code * 260 + c];
    }
}

// ---------------------------------------------------------------------------
// Kernel 3: distance GEMM + per-block argmin.
// Grid (256 row-blocks, 8 code-blocks). 256 thr = 16x16 (tx,ty).
// Thread tile: rows {ty+16i, i<8} x code-pairs {2*(tx+16j), j<4}.
// smem c-major: z[c][128 rows], e[c][128 codes] (e pre-scaled by -2).
// FMA2 vectorized over code pairs: ev = LDS.64 lane-stride 2 (conflict-free),
// zv = 2-address broadcast LDS.32 + dup.
// ---------------------------------------------------------------------------
__global__ void __launch_bounds__(256, 1)
k_main2(const float* __restrict__ z_e)
{
    extern __shared__ float sm[];
    float* zb[2] = { sm,            sm + ZPAN     };
    float* ebuf[2] = { sm + 2*ZPAN, sm + 3*ZPAN   };
    __shared__ float en_s[BK];

    const int tid = threadIdx.x;
    const int tx = tid & 15, ty = tid >> 4;
    const int r0  = blockIdx.x * BR;
    const int cb  = blockIdx.y;
    const int b   = r0 >> 10;
    const int hw0 = r0 & 1023;

    if (tid < BK) en_s[tid] = g_enorm[cb * BK + tid];

    // issue panel 0 loads
    {
        unsigned zdst = smem_u32(zb[0]);
        unsigned edst = smem_u32(ebuf[0]);
        for (int t = tid; t < PC * 32; t += 256) {
            int c = t >> 5;                 // 0..63
            int q = (t & 31) << 2;          // 0..124 step 4
            cp16(zdst + (c * BR + q) * 4,
                 z_e + (((size_t)(b * C_DIM + c)) << 10) + hw0 + q);
            cp16(edst + (c * BK + q) * 4,
                 g_embT2 + (size_t)c * K_CODES + cb * BK + q);
        }
        asm volatile("cp.async.commit_group;");
    }

    ull acc[8][4];
    #pragma unroll
    for (int i = 0; i < 8; i++)
        #pragma unroll
        for (int j = 0; j < 4; j++) acc[i][j] = 0ull;

    for (int p = 0; p < NPAN; p++) {
        asm volatile("cp.async.wait_group 0;");
        __syncthreads();
        const float* zp = zb[p & 1];
        const float* ep = ebuf[p & 1];
        if (p + 1 < NPAN) {
            unsigned zdst = smem_u32(zb[(p + 1) & 1]);
            unsigned edst = smem_u32(ebuf[(p + 1) & 1]);
            int c0 = (p + 1) * PC;
            for (int t = tid; t < PC * 32; t += 256) {
                int c = t >> 5;
                int q = (t & 31) << 2;
                cp16(zdst + (c * BR + q) * 4,
                     z_e + (((size_t)(b * C_DIM + c0 + c)) << 10) + hw0 + q);
                cp16(edst + (c * BK + q) * 4,
                     g_embT2 + (size_t)(c0 + c) * K_CODES + cb * BK + q);
            }
            asm volatile("cp.async.commit_group;");
        }

        #pragma unroll 4
        for (int c = 0; c < PC; c++) {
            const float* zr = zp + c * BR;
            const float* er = ep + c * BK;
            ull zz[8], ev[4];
            #pragma unroll
            for (int i = 0; i < 8; i++) zz[i] = dup2(zr[ty + 16 * i]);
            #pragma unroll
            for (int j = 0; j < 4; j++)
                ev[j] = *(const ull*)(er + 2 * (tx + 16 * j));
            #pragma unroll
            for (int i = 0; i < 8; i++)
                #pragma unroll
                for (int j = 0; j < 4; j++)
                    fma2(acc[i][j], zz[i], ev[j]);
        }
        __syncthreads();
    }

    // epilogue: dist = ||e||^2 + (-2 z.e)   (||z||^2 argmin-invariant)
    #pragma unroll
    for (int i = 0; i < 8; i++) {
        float best = FLT_MAX;
        int   bidx = 0x7fffffff;
        #pragma unroll
        for (int j = 0; j < 4; j++) {
            int lc = 2 * (tx + 16 * j);
            float lo = __uint_as_float((unsigned)acc[i][j]);
            float hi = __uint_as_float((unsigned)(acc[i][j] >> 32));
            float d0 = en_s[lc]     + lo;
            float d1 = en_s[lc + 1] + hi;
            int k0 = cb * BK + lc;
            if (d0 < best || (d0 == best && k0 < bidx))     { best = d0; bidx = k0; }
            if (d1 < best || (d1 == best && k0 + 1 < bidx)) { best = d1; bidx = k0 + 1; }
        }
        // reduce across tx (16 lanes; xor<=8 stays within the ty half)
        #pragma unroll
        for (int m = 1; m < 16; m <<= 1) {
            float ov = __shfl_xor_sync(0xffffffffu, best, m);
            int   oi = __shfl_xor_sync(0xffffffffu, bidx, m);
            if (ov < best || (ov == best && oi < bidx)) { best = ov; bidx = oi; }
        }
        if (tx == 0) {
            int row = r0 + ty + 16 * i;
            g_pd[cb * N_ROWS + row] = best;
            g_pi[cb * N_ROWS + row] = bidx;
        }
    }
}

// ---------------------------------------------------------------------------
// Kernel 4: reduce 8 code-block partials per row -> final index
// ---------------------------------------------------------------------------
__global__ void k_pick(float* __restrict__ out_idx_f) {
    int row = blockIdx.x * 256 + threadIdx.x;
    float best = FLT_MAX;
    int   bidx = 0x7fffffff;
    #pragma unroll
    for (int cb = 0; cb < NCB; cb++) {
        float d = g_pd[cb * N_ROWS + row];
        int   k = g_pi[cb * N_ROWS + row];
        if (d < best || (d == best && k < bidx)) { best = d; bidx = k; }
    }
    g_idx[row] = bidx;
    out_idx_f[row] = (float)bidx;
}

// ---------------------------------------------------------------------------
// Kernel 5: gather z_q = emb[idx], write res in NCHW, accumulate sq-diff.
// ---------------------------------------------------------------------------
__global__ void __launch_bounds__(256)
k_gather(const float* __restrict__ z_e, const float* __restrict__ emb,
         float* __restrict__ res)
{
    extern __shared__ float esm[];      // 128 x 257
    __shared__ int   idx_sm[128];
    __shared__ float wsum[8];

    const int tid = threadIdx.x;
    const int r0  = blockIdx.x * 128;
    const int b   = r0 >> 10;
    const int hw0 = r0 & 1023;

    if (tid < 128) idx_sm[tid] = g_idx[r0 + tid];
    __syncthreads();

    for (int i = tid; i < 128 * 256; i += 256) {
        int r = i >> 8, c = i & 255;
        esm[r * 257 + c] = emb[idx_sm[r] * C_DIM + c];
    }
    __syncthreads();

    float acc = 0.0f;
    const int r     = tid & 127;
    const int chalf = tid >> 7;
    for (int cc = 0; cc < 256; cc += 2) {
        int c = cc + chalf;
        float v = esm[r * 257 + c];
        size_t gi = (((size_t)(b * C_DIM + c)) << 10) + hw0 + r;
        float zv = z_e[gi];
        res[gi] = v;
        float df = v - zv;
        acc += df * df;
    }

    #pragma unroll
    for (int m = 16; m; m >>= 1) acc += __shfl_xor_sync(0xffffffffu, acc, m);
    if ((tid & 31) == 0) wsum[tid >> 5] = acc;
    __syncthreads();
    if (tid == 0) {
        float s = 0.0f;
        #pragma unroll
        for (int w = 0; w < 8; w++) s += wsum[w];
        g_partial[blockIdx.x] = s;
    }
}

// ---------------------------------------------------------------------------
// Kernel 6: final loss = 1.25 * mean(sq-diff)
// ---------------------------------------------------------------------------
__global__ void k_loss(float* __restrict__ out_loss) {
    __shared__ float s[256];
    int tid = threadIdx.x;
    s[tid] = g_partial[tid];
    __syncthreads();
    for (int st = 128; st > 0; st >>= 1) {
        if (tid < st) s[tid] += s[tid + st];
        __syncthreads();
    }
    if (tid == 0) out_loss[0] = 1.25f * (s[0] / 8388608.0f);
}

// ---------------------------------------------------------------------------
extern "C" void kernel_launch(void* const* d_in, const int* in_sizes, int n_in,
                              void* d_out, int out_size)
{
    const float* z_e = (const float*)d_in[0];   // (32, 256, 32, 32) fp32
    const float* emb = (const float*)d_in[1];   // (1024, 256) fp32

    float* out  = (float*)d_out;
    float* res  = out;                           // 8,388,608 floats
    float* loss = out + 8388608;                 // 1 float
    float* idxf = out + 8388609;                 // 32,768 floats (indices)

    cudaFuncSetAttribute(k_main2,  cudaFuncAttributeMaxDynamicSharedMemorySize, SMEM_MAIN);
    cudaFuncSetAttribute(k_gather, cudaFuncAttributeMaxDynamicSharedMemorySize, SMEM_GATHER);

    k_enorm    <<<K_CODES / 8, 256>>>(emb);
    k_transpose<<<K_CODES / 32, 256>>>(emb);
    k_main2    <<<dim3(N_ROWS / BR, NCB), 256, SMEM_MAIN>>>(z_e);
    k_pick     <<<N_ROWS / 256, 256>>>(idxf);
    k_gather   <<<N_ROWS / 128, 256, SMEM_GATHER>>>(z_e, emb, res);
    k_loss     <<<1, 256>>>(loss);
}